// round 17
// baseline (speedup 1.0000x reference)
#include <cuda_runtime.h>

#define NG    64
#define DIM   240
#define NF4   60          // float4 per row
#define NSTAT 16
#define EPS   1e-5f

// Scratch (no device allocation). g_sums zero at load; finalize re-zeroes.
__device__ float g_sums[NG * NSTAT];
__device__ float g_A[NG * DIM];
__device__ float g_B[NG * DIM];
__device__ int   g_bounds[NG + 1];

// g_bounds[g] = first row index with batch[row] >= g  (lower bound).
__global__ void bounds_kernel(const int* __restrict__ batch, int n) {
    int g = threadIdx.x;
    if (g > NG) return;
    int lo = 0, hi = n;
    while (lo < hi) {
        int mid = (lo + hi) >> 1;
        if (__ldg(batch + mid) < g) lo = mid + 1; else hi = mid;
    }
    g_bounds[g] = lo;
}

// Stat id for a non-seg0 column c (64..239).
__device__ __forceinline__ int stat_of(int c) {
    return (c < 160) ? (2 + (c - 64) % 3) : (5 + (c - 160) % 5);
}

// Branch-free streaming stats. Warp processes rows [r0,r1); graph segments
// come from g_bounds (no batch loads, no load-dependent branches).
// Row pair = 4x LDG.128 over flat float4 stream: slot (k,lane) covers
// j = 32k+lane in [0,120), column group c4 = j%60 (fixed per slot).
// c4<16 -> seg0 (needs sumsq); 16..39 -> seg1; 40..59 -> seg2.
__global__ void __launch_bounds__(256) stats_kernel(const float4* __restrict__ x4,
                                                    int n) {
    __shared__ float sbins[8][NSTAT];
    const int lane = threadIdx.x & 31;
    float* bins = sbins[threadIdx.x >> 5];
    if (lane < NSTAT) bins[lane] = 0.f;
    __syncwarp();

    // Per-slot constants
    bool valid[4], z[4];
    int  c4k[4];
#pragma unroll
    for (int k = 0; k < 4; k++) {
        int j = 32 * k + lane;
        valid[k] = j < 2 * NF4;
        int c4 = j % NF4;
        c4k[k] = c4;
        z[k] = c4 < 16;
    }

    const int wid = (blockIdx.x * blockDim.x + threadIdx.x) >> 5;
    const int nw  = (gridDim.x * blockDim.x) >> 5;
    const int rpw = (n + nw - 1) / nw;
    int r = wid * rpw;
    const int r1 = min(r + rpw, n);

    while (r < r1) {
        // graph of row r: largest g with g_bounds[g] <= r
        int lo = 0, hi = NG - 1;
        while (lo < hi) {
            int mid = (lo + hi + 1) >> 1;
            if (g_bounds[mid] <= r) lo = mid; else hi = mid - 1;
        }
        const int g = lo;
        const int seg_end = min(r1, g_bounds[g + 1]);
        const int m = seg_end - r;

        float s[4][4] = {{0.f,0.f,0.f,0.f},{0.f,0.f,0.f,0.f},
                         {0.f,0.f,0.f,0.f},{0.f,0.f,0.f,0.f}};
        float sq[4] = {0.f, 0.f, 0.f, 0.f};

        int pairs = m >> 1;
        const float4* base = x4 + (size_t)r * NF4;
        for (int p = 0; p < pairs; p++) {
#pragma unroll
            for (int k = 0; k < 4; k++) {
                if (valid[k]) {
                    float4 v = __ldg(base + 32 * k + lane);
                    s[k][0] += v.x; s[k][1] += v.y;
                    s[k][2] += v.z; s[k][3] += v.w;
                    if (z[k]) {
                        sq[k] = fmaf(v.x, v.x, sq[k]);
                        sq[k] = fmaf(v.y, v.y, sq[k]);
                        sq[k] = fmaf(v.z, v.z, sq[k]);
                        sq[k] = fmaf(v.w, v.w, sq[k]);
                    }
                }
            }
            base += 2 * NF4;
        }
        if (m & 1) {           // remainder single row: slots k=0,1 with j<60
#pragma unroll
            for (int k = 0; k < 2; k++) {
                if (32 * k + lane < NF4) {
                    float4 v = __ldg(base + 32 * k + lane);
                    s[k][0] += v.x; s[k][1] += v.y;
                    s[k][2] += v.z; s[k][3] += v.w;
                    if (z[k]) {
                        sq[k] = fmaf(v.x, v.x, sq[k]);
                        sq[k] = fmaf(v.y, v.y, sq[k]);
                        sq[k] = fmaf(v.z, v.z, sq[k]);
                        sq[k] = fmaf(v.w, v.w, sq[k]);
                    }
                }
            }
        }
        r = seg_end;

        // Flush this graph segment: scatter into per-warp shared bins.
#pragma unroll
        for (int k = 0; k < 4; k++) {
            if (valid[k]) {
                if (z[k]) {
                    atomicAdd(&bins[0], s[k][0] + s[k][1] + s[k][2] + s[k][3]);
                    atomicAdd(&bins[1], sq[k]);
                } else {
                    int cbase = 4 * c4k[k];
#pragma unroll
                    for (int j = 0; j < 4; j++)
                        atomicAdd(&bins[stat_of(cbase + j)], s[k][j]);
                }
            }
        }
        __syncwarp();
        if (lane < 10) atomicAdd(&g_sums[g * NSTAT + lane], bins[lane]);
        if (lane == 10) atomicAdd(&g_sums[g * NSTAT + 10], (float)m);
        __syncwarp();
        if (lane < NSTAT) bins[lane] = 0.f;
        __syncwarp();
    }
}

// Build per-(graph, col) affine params (y = x*a + b), then re-zero stats
// so the next graph replay starts from zeros.
__global__ void finalize_kernel(const float* __restrict__ weight,
                                const float* __restrict__ bias) {
    int g = blockIdx.x;
    int c = threadIdx.x;
    float* sm = g_sums + g * NSTAT;
    if (c < DIM) {
        const float* s = sm;
        float cnt = fmaxf(s[10], 1.f);
        float a, b;
        if (c < 64) {
            float invn = 1.f / (cnt * 64.f);
            float mean = s[0] * invn;
            float var  = fmaxf(fmaf(-mean, mean, s[1] * invn), 0.f);
            float inv  = 1.f / (sqrtf(var) + EPS);
            float w = weight[c];
            a = w * inv;
            b = bias[c] - mean * a;
        } else if (c < 160) {
            int cc = c - 64;
            int d = cc % 3, m = cc / 3;
            float mean = s[2 + d] / (cnt * 32.f);
            float w = weight[64 + m];
            a = w;
            b = -mean * w;
        } else {
            int cc = c - 160;
            int d = cc % 5, m = cc / 5;
            float mean = s[5 + d] / (cnt * 16.f);
            float w = weight[96 + m];
            a = w;
            b = -mean * w;
        }
        g_A[g * DIM + c] = a;
        g_B[g * DIM + c] = b;
    }
    __syncthreads();
    if (c < NSTAT) sm[c] = 0.f;
}

// Streaming pass: y4 = fma(x4, a4[g], b4[g]).
__global__ void __launch_bounds__(256) apply_kernel(const float4* __restrict__ x4,
                                                    const int* __restrict__ batch,
                                                    float4* __restrict__ out4,
                                                    int n4) {
    int stride = gridDim.x * blockDim.x;
#pragma unroll 4
    for (int i = blockIdx.x * blockDim.x + threadIdx.x; i < n4; i += stride) {
        unsigned u   = (unsigned)i;
        unsigned row = u / 60u;
        unsigned c4  = u - row * 60u;
        unsigned off = (unsigned)__ldg(batch + row) * DIM + c4 * 4u;
        const float4 a = __ldg(reinterpret_cast<const float4*>(g_A + off));
        const float4 b = __ldg(reinterpret_cast<const float4*>(g_B + off));
        float4 v = x4[i];
        v.x = fmaf(v.x, a.x, b.x);
        v.y = fmaf(v.y, a.y, b.y);
        v.z = fmaf(v.z, a.z, b.z);
        v.w = fmaf(v.w, a.w, b.w);
        out4[i] = v;
    }
}

extern "C" void kernel_launch(void* const* d_in, const int* in_sizes, int n_in,
                              void* d_out, int out_size) {
    const float* x      = (const float*)d_in[0];
    const int*   batch  = (const int*)d_in[1];
    const float* weight = (const float*)d_in[2];
    const float* bias   = (const float*)d_in[3];
    (void)n_in; (void)out_size;

    int n  = in_sizes[1];
    int n4 = n * (DIM / 4);

    bounds_kernel<<<1, 128>>>(batch, n);
    stats_kernel<<<592, 256>>>((const float4*)x, n);
    finalize_kernel<<<NG, DIM>>>(weight, bias);
    apply_kernel<<<1184, 256>>>((const float4*)x, batch, (float4*)d_out, n4);
}